// round 2
// baseline (speedup 1.0000x reference)
#include <cuda_runtime.h>
#include <cuda_bf16.h>

#define T_MAX 4096
#define ACC_BLOCKS 148
#define ACC_THREADS 1024

// Global accumulators (persist across replays -> zeroed every launch)
__device__ float  g_exp[T_MAX];   // sum of exp(risk) per time bucket
__device__ int    g_d[T_MAX];     // event count per time bucket
__device__ double g_evr;          // sum of risk over events
__device__ int    g_is64;         // 1 if time/event are int64, 0 if int32

__global__ void zero_kernel() {
    int i = blockIdx.x * blockDim.x + threadIdx.x;
    if (i < T_MAX) { g_exp[i] = 0.0f; g_d[i] = 0; }
    if (i == 0) g_evr = 0.0;
}

// Detect element width of `time`: values are in [0, 4096), so if the buffer
// is int64, every odd 32-bit word is 0. If int32, odd words are random times
// (all-zero over 64K samples has probability ~(1/4096)^64K ~ 0).
__global__ void detect_kernel(const int* __restrict__ time32, int n) {
    __shared__ int s_or;
    if (threadIdx.x == 0) s_or = 0;
    __syncthreads();

    int nw = n >> 1;                 // safe word-pair count in either layout
    if (nw > 65536) nw = 65536;
    int v = 0;
    for (int i = threadIdx.x; i < nw; i += blockDim.x)
        v |= time32[2 * i + 1];

    #pragma unroll
    for (int off = 16; off; off >>= 1)
        v |= __shfl_down_sync(0xffffffffu, v, off);
    if ((threadIdx.x & 31) == 0) atomicOr(&s_or, v);
    __syncthreads();
    if (threadIdx.x == 0) g_is64 = (s_or == 0) ? 1 : 0;
}

__global__ void __launch_bounds__(ACC_THREADS)
accum_kernel(const float* __restrict__ risk,
             const void* __restrict__ time_raw,
             const void* __restrict__ event_raw,
             int n)
{
    __shared__ float s_exp[T_MAX];
    __shared__ int   s_d[T_MAX];
    __shared__ float s_wsum[32];

    for (int i = threadIdx.x; i < T_MAX; i += ACC_THREADS) {
        s_exp[i] = 0.0f;
        s_d[i] = 0;
    }
    __syncthreads();

    const int nchunk = n >> 2;          // 4 elements per chunk
    const int stride = gridDim.x * blockDim.x;
    const int gtid = blockIdx.x * blockDim.x + threadIdx.x;
    const int is64 = g_is64;

    const float4* __restrict__ risk4 = (const float4*)risk;

    float evr = 0.0f;

    if (!is64) {
        const int4* __restrict__ time4  = (const int4*)time_raw;
        const int4* __restrict__ event4 = (const int4*)event_raw;
        for (int c = gtid; c < nchunk; c += stride) {
            float4 r = __ldg(&risk4[c]);
            int4 t = __ldg(&time4[c]);
            int4 e = __ldg(&event4[c]);

            int ta = t.x & (T_MAX-1), tb = t.y & (T_MAX-1);
            int tc = t.z & (T_MAX-1), td = t.w & (T_MAX-1);

            atomicAdd(&s_exp[ta], __expf(r.x));
            atomicAdd(&s_exp[tb], __expf(r.y));
            atomicAdd(&s_exp[tc], __expf(r.z));
            atomicAdd(&s_exp[td], __expf(r.w));

            if (e.x) { atomicAdd(&s_d[ta], 1); evr += r.x; }
            if (e.y) { atomicAdd(&s_d[tb], 1); evr += r.y; }
            if (e.z) { atomicAdd(&s_d[tc], 1); evr += r.z; }
            if (e.w) { atomicAdd(&s_d[td], 1); evr += r.w; }
        }
        int rem = n & 3;
        if (blockIdx.x == 0 && threadIdx.x < rem) {
            int i = (nchunk << 2) + threadIdx.x;
            const int* t32 = (const int*)time_raw;
            const int* e32 = (const int*)event_raw;
            float r = __ldg(&risk[i]);
            int t = t32[i] & (T_MAX-1);
            atomicAdd(&s_exp[t], __expf(r));
            if (e32[i]) { atomicAdd(&s_d[t], 1); evr += r; }
        }
    } else {
        const int4* __restrict__ time4  = (const int4*)time_raw;   // 2 int64 per int4
        const int4* __restrict__ event4 = (const int4*)event_raw;
        for (int c = gtid; c < nchunk; c += stride) {
            float4 r = __ldg(&risk4[c]);
            int4 t0 = __ldg(&time4[2*c]);
            int4 t1 = __ldg(&time4[2*c + 1]);
            int4 e0 = __ldg(&event4[2*c]);
            int4 e1 = __ldg(&event4[2*c + 1]);

            int ta = t0.x & (T_MAX-1), tb = t0.z & (T_MAX-1);
            int tc = t1.x & (T_MAX-1), td = t1.z & (T_MAX-1);

            atomicAdd(&s_exp[ta], __expf(r.x));
            atomicAdd(&s_exp[tb], __expf(r.y));
            atomicAdd(&s_exp[tc], __expf(r.z));
            atomicAdd(&s_exp[td], __expf(r.w));

            if (e0.x) { atomicAdd(&s_d[ta], 1); evr += r.x; }
            if (e0.z) { atomicAdd(&s_d[tb], 1); evr += r.y; }
            if (e1.x) { atomicAdd(&s_d[tc], 1); evr += r.z; }
            if (e1.z) { atomicAdd(&s_d[td], 1); evr += r.w; }
        }
        int rem = n & 3;
        if (blockIdx.x == 0 && threadIdx.x < rem) {
            int i = (nchunk << 2) + threadIdx.x;
            const long long* t64 = (const long long*)time_raw;
            const long long* e64 = (const long long*)event_raw;
            float r = __ldg(&risk[i]);
            int t = (int)t64[i] & (T_MAX-1);
            atomicAdd(&s_exp[t], __expf(r));
            if (e64[i]) { atomicAdd(&s_d[t], 1); evr += r; }
        }
    }

    // Reduce evr: warp shuffle, then cross-warp via shared
    int lane = threadIdx.x & 31, wid = threadIdx.x >> 5;
    #pragma unroll
    for (int off = 16; off; off >>= 1)
        evr += __shfl_down_sync(0xffffffffu, evr, off);
    if (lane == 0) s_wsum[wid] = evr;

    __syncthreads();   // covers s_wsum visibility AND s_exp/s_d completion

    if (wid == 0) {
        float s = (lane < (ACC_THREADS / 32)) ? s_wsum[lane] : 0.0f;
        #pragma unroll
        for (int off = 16; off; off >>= 1)
            s += __shfl_down_sync(0xffffffffu, s, off);
        if (lane == 0) atomicAdd(&g_evr, (double)s);
    }

    // Flush block-private histograms to global (skip zeros)
    for (int i = threadIdx.x; i < T_MAX; i += ACC_THREADS) {
        float v = s_exp[i];
        if (v != 0.0f) atomicAdd(&g_exp[i], v);
        int d = s_d[i];
        if (d) atomicAdd(&g_d[i], d);
    }
}

// Single block, 1024 threads. j = 4095 - t (reversed index) so the suffix
// sum over time becomes an inclusive prefix scan over j. Double precision.
__global__ void __launch_bounds__(1024)
finalize_kernel(float* __restrict__ out)
{
    __shared__ double s_scan[32];
    __shared__ double s_acc[32];
    __shared__ long long s_totd[32];

    const int tid = threadIdx.x;
    const int lane = tid & 31, wid = tid >> 5;

    double local[4];
    double run = 0.0;
    #pragma unroll
    for (int k = 0; k < 4; k++) {
        int j = tid * 4 + k;
        int t = (T_MAX - 1) - j;
        run += (double)g_exp[t];
        local[k] = run;
    }

    // Inclusive scan of per-thread totals (warp shuffle then cross-warp)
    double v = run;
    #pragma unroll
    for (int off = 1; off < 32; off <<= 1) {
        double nv = __shfl_up_sync(0xffffffffu, v, off);
        if (lane >= off) v += nv;
    }
    if (lane == 31) s_scan[wid] = v;
    __syncthreads();
    if (wid == 0) {
        double w = s_scan[lane];
        #pragma unroll
        for (int off = 1; off < 32; off <<= 1) {
            double nw = __shfl_up_sync(0xffffffffu, w, off);
            if (lane >= off) w += nw;
        }
        s_scan[lane] = w;
    }
    __syncthreads();

    double excl = (v - run) + (wid > 0 ? s_scan[wid - 1] : 0.0);

    double acc = 0.0;
    long long totd = 0;
    #pragma unroll
    for (int k = 0; k < 4; k++) {
        int j = tid * 4 + k;
        int t = (T_MAX - 1) - j;
        int d = g_d[t];
        if (d) {
            acc += (double)d * log(excl + local[k]);
            totd += d;
        }
    }

    // Block reduce acc and totd
    #pragma unroll
    for (int off = 16; off; off >>= 1) {
        acc  += __shfl_down_sync(0xffffffffu, acc, off);
        totd += __shfl_down_sync(0xffffffffu, totd, off);
    }
    if (lane == 0) { s_acc[wid] = acc; s_totd[wid] = totd; }
    __syncthreads();
    if (wid == 0) {
        double a = s_acc[lane];
        long long d = s_totd[lane];
        #pragma unroll
        for (int off = 16; off; off >>= 1) {
            a += __shfl_down_sync(0xffffffffu, a, off);
            d += __shfl_down_sync(0xffffffffu, d, off);
        }
        if (lane == 0)
            out[0] = (d > 0) ? (float)(a - g_evr) : 0.0f;
    }
}

extern "C" void kernel_launch(void* const* d_in, const int* in_sizes, int n_in,
                              void* d_out, int out_size)
{
    const float* risk  = (const float*)d_in[0];
    const void*  time  = d_in[1];
    const void*  event = d_in[2];
    int n = in_sizes[0];

    zero_kernel<<<(T_MAX + 511) / 512, 512>>>();
    detect_kernel<<<1, 1024>>>((const int*)time, n);
    accum_kernel<<<ACC_BLOCKS, ACC_THREADS>>>(risk, time, event, n);
    finalize_kernel<<<1, 1024>>>((float*)d_out);
}

// round 3
// speedup vs baseline: 2.3687x; 2.3687x over previous
#include <cuda_runtime.h>
#include <cuda_bf16.h>

#define T_MAX 4096
#define ACC_BLOCKS 148
#define ACC_THREADS 1024

// Global accumulators (persist across replays -> zeroed every launch)
__device__ float  g_exp[T_MAX];   // sum of exp(risk) per time bucket
__device__ int    g_d[T_MAX];     // event count per time bucket
__device__ double g_evr;          // sum of risk over events
__device__ int    g_is64;         // 1 if time/event are int64, 0 if int32

// Zero accumulators; block 0 additionally detects element width of `time`.
// Times are in [0,4096): if the buffer is int64, every odd 32-bit word is 0.
// If int32, odd words are random times (all-zero over 2048 samples has
// probability ~(1/4096)^2048 ~ 0). 16KB sampled read — negligible.
__global__ void init_kernel(const int* __restrict__ time32, int n) {
    int i = blockIdx.x * blockDim.x + threadIdx.x;
    if (i < T_MAX) { g_exp[i] = 0.0f; g_d[i] = 0; }
    if (i == 0) g_evr = 0.0;

    if (blockIdx.x == 0) {
        __shared__ int s_or;
        if (threadIdx.x == 0) s_or = 0;
        __syncthreads();

        int nw = n >> 1;
        if (nw > 2048) nw = 2048;
        int v = 0;
        for (int j = threadIdx.x; j < nw; j += blockDim.x)
            v |= time32[2 * j + 1];

        #pragma unroll
        for (int off = 16; off; off >>= 1)
            v |= __shfl_down_sync(0xffffffffu, v, off);
        if ((threadIdx.x & 31) == 0 && v) atomicOr(&s_or, v);
        __syncthreads();
        if (threadIdx.x == 0) g_is64 = (s_or == 0) ? 1 : 0;
    }
}

__global__ void __launch_bounds__(ACC_THREADS)
accum_kernel(const float* __restrict__ risk,
             const void* __restrict__ time_raw,
             const void* __restrict__ event_raw,
             int n)
{
    __shared__ float s_exp[T_MAX];
    __shared__ int   s_d[T_MAX];
    __shared__ float s_wsum[32];

    for (int i = threadIdx.x; i < T_MAX; i += ACC_THREADS) {
        s_exp[i] = 0.0f;
        s_d[i] = 0;
    }
    __syncthreads();

    const int nchunk = n >> 2;          // 4 elements per chunk
    const int stride = gridDim.x * blockDim.x;
    const int gtid = blockIdx.x * blockDim.x + threadIdx.x;
    const int is64 = g_is64;

    const float4* __restrict__ risk4 = (const float4*)risk;

    float evr = 0.0f;

    if (!is64) {
        const int4* __restrict__ time4  = (const int4*)time_raw;
        const int4* __restrict__ event4 = (const int4*)event_raw;
        for (int c = gtid; c < nchunk; c += stride) {
            float4 r = __ldg(&risk4[c]);
            int4 t = __ldg(&time4[c]);
            int4 e = __ldg(&event4[c]);

            int ta = t.x & (T_MAX-1), tb = t.y & (T_MAX-1);
            int tc = t.z & (T_MAX-1), td = t.w & (T_MAX-1);

            atomicAdd(&s_exp[ta], __expf(r.x));
            atomicAdd(&s_exp[tb], __expf(r.y));
            atomicAdd(&s_exp[tc], __expf(r.z));
            atomicAdd(&s_exp[td], __expf(r.w));

            if (e.x) { atomicAdd(&s_d[ta], 1); evr += r.x; }
            if (e.y) { atomicAdd(&s_d[tb], 1); evr += r.y; }
            if (e.z) { atomicAdd(&s_d[tc], 1); evr += r.z; }
            if (e.w) { atomicAdd(&s_d[td], 1); evr += r.w; }
        }
        int rem = n & 3;
        if (blockIdx.x == 0 && threadIdx.x < rem) {
            int i = (nchunk << 2) + threadIdx.x;
            const int* t32 = (const int*)time_raw;
            const int* e32 = (const int*)event_raw;
            float r = __ldg(&risk[i]);
            int t = t32[i] & (T_MAX-1);
            atomicAdd(&s_exp[t], __expf(r));
            if (e32[i]) { atomicAdd(&s_d[t], 1); evr += r; }
        }
    } else {
        const int4* __restrict__ time4  = (const int4*)time_raw;   // 2 int64 per int4
        const int4* __restrict__ event4 = (const int4*)event_raw;
        for (int c = gtid; c < nchunk; c += stride) {
            float4 r = __ldg(&risk4[c]);
            int4 t0 = __ldg(&time4[2*c]);
            int4 t1 = __ldg(&time4[2*c + 1]);
            int4 e0 = __ldg(&event4[2*c]);
            int4 e1 = __ldg(&event4[2*c + 1]);

            int ta = t0.x & (T_MAX-1), tb = t0.z & (T_MAX-1);
            int tc = t1.x & (T_MAX-1), td = t1.z & (T_MAX-1);

            atomicAdd(&s_exp[ta], __expf(r.x));
            atomicAdd(&s_exp[tb], __expf(r.y));
            atomicAdd(&s_exp[tc], __expf(r.z));
            atomicAdd(&s_exp[td], __expf(r.w));

            if (e0.x) { atomicAdd(&s_d[ta], 1); evr += r.x; }
            if (e0.z) { atomicAdd(&s_d[tb], 1); evr += r.y; }
            if (e1.x) { atomicAdd(&s_d[tc], 1); evr += r.z; }
            if (e1.z) { atomicAdd(&s_d[td], 1); evr += r.w; }
        }
        int rem = n & 3;
        if (blockIdx.x == 0 && threadIdx.x < rem) {
            int i = (nchunk << 2) + threadIdx.x;
            const long long* t64 = (const long long*)time_raw;
            const long long* e64 = (const long long*)event_raw;
            float r = __ldg(&risk[i]);
            int t = (int)t64[i] & (T_MAX-1);
            atomicAdd(&s_exp[t], __expf(r));
            if (e64[i]) { atomicAdd(&s_d[t], 1); evr += r; }
        }
    }

    // Reduce evr: warp shuffle, then cross-warp via shared
    int lane = threadIdx.x & 31, wid = threadIdx.x >> 5;
    #pragma unroll
    for (int off = 16; off; off >>= 1)
        evr += __shfl_down_sync(0xffffffffu, evr, off);
    if (lane == 0) s_wsum[wid] = evr;

    __syncthreads();   // covers s_wsum visibility AND s_exp/s_d completion

    if (wid == 0) {
        float s = (lane < (ACC_THREADS / 32)) ? s_wsum[lane] : 0.0f;
        #pragma unroll
        for (int off = 16; off; off >>= 1)
            s += __shfl_down_sync(0xffffffffu, s, off);
        if (lane == 0) atomicAdd(&g_evr, (double)s);
    }

    // Flush block-private histograms to global (skip zeros)
    for (int i = threadIdx.x; i < T_MAX; i += ACC_THREADS) {
        float v = s_exp[i];
        if (v != 0.0f) atomicAdd(&g_exp[i], v);
        int d = s_d[i];
        if (d) atomicAdd(&g_d[i], d);
    }
}

// Single block, 1024 threads. j = 4095 - t (reversed index) so the suffix
// sum over time becomes an inclusive prefix scan over j.
// Float scan + logf (tolerance is 1e-3; float path error ~1e-6), with only
// the final 4096-term accumulation in double.
__global__ void __launch_bounds__(1024)
finalize_kernel(float* __restrict__ out)
{
    __shared__ float s_scan[32];
    __shared__ double s_acc[32];
    __shared__ int s_totd[32];

    const int tid = threadIdx.x;
    const int lane = tid & 31, wid = tid >> 5;

    float local[4];
    float run = 0.0f;
    #pragma unroll
    for (int k = 0; k < 4; k++) {
        int t = (T_MAX - 1) - (tid * 4 + k);
        run += g_exp[t];
        local[k] = run;
    }

    // Inclusive scan of per-thread totals (warp shuffle then cross-warp)
    float v = run;
    #pragma unroll
    for (int off = 1; off < 32; off <<= 1) {
        float nv = __shfl_up_sync(0xffffffffu, v, off);
        if (lane >= off) v += nv;
    }
    if (lane == 31) s_scan[wid] = v;
    __syncthreads();
    if (wid == 0) {
        float w = s_scan[lane];
        #pragma unroll
        for (int off = 1; off < 32; off <<= 1) {
            float nw = __shfl_up_sync(0xffffffffu, w, off);
            if (lane >= off) w += nw;
        }
        s_scan[lane] = w;
    }
    __syncthreads();

    float excl = (v - run) + (wid > 0 ? s_scan[wid - 1] : 0.0f);

    double acc = 0.0;
    int totd = 0;
    #pragma unroll
    for (int k = 0; k < 4; k++) {
        int t = (T_MAX - 1) - (tid * 4 + k);
        int d = g_d[t];
        if (d) {
            acc += (double)((float)d * logf(excl + local[k]));
            totd += d;
        }
    }

    // Block reduce acc (double) and totd (int)
    #pragma unroll
    for (int off = 16; off; off >>= 1) {
        acc  += __shfl_down_sync(0xffffffffu, acc, off);
        totd += __shfl_down_sync(0xffffffffu, totd, off);
    }
    if (lane == 0) { s_acc[wid] = acc; s_totd[wid] = totd; }
    __syncthreads();
    if (wid == 0) {
        double a = s_acc[lane];
        int d = s_totd[lane];
        #pragma unroll
        for (int off = 16; off; off >>= 1) {
            a += __shfl_down_sync(0xffffffffu, a, off);
            d += __shfl_down_sync(0xffffffffu, d, off);
        }
        if (lane == 0)
            out[0] = (d > 0) ? (float)(a - g_evr) : 0.0f;
    }
}

extern "C" void kernel_launch(void* const* d_in, const int* in_sizes, int n_in,
                              void* d_out, int out_size)
{
    const float* risk  = (const float*)d_in[0];
    const void*  time  = d_in[1];
    const void*  event = d_in[2];
    int n = in_sizes[0];

    init_kernel<<<(T_MAX + 1023) / 1024, 1024>>>((const int*)time, n);
    accum_kernel<<<ACC_BLOCKS, ACC_THREADS>>>(risk, time, event, n);
    finalize_kernel<<<1, 1024>>>((float*)d_out);
}